// round 16
// baseline (speedup 1.0000x reference)
#include <cuda_runtime.h>
#include <cuda_fp16.h>
#include <cstdint>

// ============================================================
// GCN, all-fp16 mma.sync, ONE persistent kernel: 64 conversion
// work items (adj/X -> fp16, per-z flags) + 6x512 GEMM tiles in
// one g-space; conversions overlap stage-0 compute. R12-proven
// API surface: 48KB smem, K=32 chunks, no memset node (counters
// zeroed by an extra prep_w block). One barrier per K-chunk.
// ============================================================

static constexpr unsigned NE = 32u * 512u * 512u;
static constexpr unsigned NW = 512u * 512u;
static constexpr int NCTA = 296;

static __device__ __half g_Xh[NE], g_Jh[NE];
static __device__ __half g_Sa[NE], g_Ha[NE], g_Sb[NE], g_Hb[NE], g_Sc[NE];
static __device__ __half g_Wth[3 * NW];
static __device__ int    g_cnt[6 * 32 * 4];
static __device__ int    g_cflag[32];
static __device__ int    g_xflag[32];

__device__ __forceinline__ uint32_t smem_u32(const void* p) {
    uint32_t a;
    asm("{ .reg .u64 t; cvta.to.shared.u64 t, %1; cvt.u32.u64 %0, t; }"
        : "=r"(a) : "l"(p));
    return a;
}

#define LDSM_X4(r0, r1, r2, r3, addr) \
    asm volatile("ldmatrix.sync.aligned.m8n8.x4.shared.b16 {%0,%1,%2,%3}, [%4];" \
                 : "=r"(r0), "=r"(r1), "=r"(r2), "=r"(r3) : "r"(addr))

#define CP_ASYNC16(dst, src) \
    asm volatile("cp.async.cg.shared.global [%0], [%1], 16;" \
                 :: "r"(dst), "l"(src) : "memory")
#define CP_COMMIT() asm volatile("cp.async.commit_group;" ::: "memory")
#define CP_WAIT(n)  asm volatile("cp.async.wait_group %0;" :: "n"(n) : "memory")

__device__ __forceinline__ void mma16816(float* d, const uint32_t* a,
                                         uint32_t b0, uint32_t b1) {
    asm volatile(
        "mma.sync.aligned.m16n8k16.row.col.f32.f16.f16.f32 "
        "{%0,%1,%2,%3}, {%4,%5,%6,%7}, {%8,%9}, {%0,%1,%2,%3};"
        : "+f"(d[0]), "+f"(d[1]), "+f"(d[2]), "+f"(d[3])
        : "r"(a[0]), "r"(a[1]), "r"(a[2]), "r"(a[3]), "r"(b0), "r"(b1));
}

static constexpr int TILE = 128 * 64;             // 8KB (128 rows x 32 fp16)
static constexpr int OFF_A = 0, OFF_B = TILE;
static constexpr int STAGE_B = 2 * TILE;          // 16KB
static constexpr int NSTG  = 3;
static constexpr int SMEM_BYTES = NSTG * STAGE_B; // 48KB (R12-proven)

__device__ __forceinline__ uint32_t sw_off(int row, int q) {
    return (uint32_t)row * 64u + (uint32_t)((q ^ ((row >> 1) & 3)) << 4);
}

// one 128x128 GEMM tile; epi: 0 plain->fp16, 1 bias+relu->fp16, 2 bias->fp32
__device__ __forceinline__
void gemm_tile(const __half* __restrict__ Ah, const __half* __restrict__ Bh,
               const float* __restrict__ bias,
               float* __restrict__ Cf, __half* __restrict__ Ch,
               long strideA, int z, int rb, int cb, int epi, uint32_t sb)
{
    const int tid  = threadIdx.x;
    const int wid  = tid >> 5;
    const int lane = tid & 31;
    const long s = 512l * 512l;
    const size_t offA = (size_t)z * strideA;
    const size_t offB = (size_t)z * s;
    const int rowBlock = rb * 128;
    const int colBlock = cb * 128;
    const int wm = (wid >> 2) * 64;
    const int wn = (wid & 3) * 32;

    const int cQ = tid & 3;
    uint32_t dOf[2];
    size_t gA[2], gB[2];
    #pragma unroll
    for (int i = 0; i < 2; ++i) {
        const int row = (tid >> 2) + i * 64;
        dOf[i] = sw_off(row, cQ);
        gA[i] = offA + (size_t)(rowBlock + row) * 512 + cQ * 8;
        gB[i] = offB + (size_t)(colBlock + row) * 512 + cQ * 8;
    }

    auto issue = [&](int c) {
        const uint32_t st = sb + (uint32_t)(c % NSTG) * STAGE_B;
        const int k0 = c * 32;
        #pragma unroll
        for (int i = 0; i < 2; ++i) {
            CP_ASYNC16(st + OFF_A + dOf[i], Ah + gA[i] + k0);
            CP_ASYNC16(st + OFF_B + dOf[i], Bh + gB[i] + k0);
        }
        CP_COMMIT();
    };

    const int lmRow = lane & 15;
    const int lmQ   = lane >> 4;
    uint32_t aRow[4], bRow[2];
    int aXr[4], bXr[2];
    #pragma unroll
    for (int ti = 0; ti < 4; ++ti) {
        const int r = wm + ti * 16 + lmRow;
        aRow[ti] = (uint32_t)r * 64u;
        aXr[ti]  = (r >> 1) & 3;
    }
    #pragma unroll
    for (int g = 0; g < 2; ++g) {
        const int r = wn + g * 16 + lmRow;
        bRow[g] = (uint32_t)r * 64u;
        bXr[g]  = (r >> 1) & 3;
    }

    float acc[4][4][4] = {};

    issue(0);
    issue(1);

    for (int c = 0; c < 16; ++c) {
        if (c == 15) { CP_WAIT(0); } else { CP_WAIT(1); }
        __syncthreads();       // also orders stage reuse for issue(c+2)
        if (c + 2 < 16) issue(c + 2);

        const uint32_t st = sb + (uint32_t)(c % NSTG) * STAGE_B;

        #pragma unroll
        for (int kk = 0; kk < 2; ++kk) {
            const int q = lmQ + kk * 2;
            uint32_t af[4][4], bb[2][4];
            #pragma unroll
            for (int g = 0; g < 2; ++g) {
                const uint32_t sw = (uint32_t)((q ^ bXr[g]) << 4);
                LDSM_X4(bb[g][0], bb[g][1], bb[g][2], bb[g][3],
                        st + OFF_B + bRow[g] + sw);
            }
            #pragma unroll
            for (int ti = 0; ti < 4; ++ti) {
                const uint32_t sw = (uint32_t)((q ^ aXr[ti]) << 4);
                LDSM_X4(af[ti][0], af[ti][1], af[ti][2], af[ti][3],
                        st + OFF_A + aRow[ti] + sw);
            }
            #pragma unroll
            for (int ti = 0; ti < 4; ++ti)
                #pragma unroll
                for (int tj = 0; tj < 4; ++tj)
                    mma16816(acc[ti][tj], af[ti],
                             bb[tj >> 1][tj & 1], bb[tj >> 1][2 + (tj & 1)]);
        }
    }

    const size_t offC = (size_t)z * s;
    #pragma unroll
    for (int ti = 0; ti < 4; ++ti) {
        const int m0 = rowBlock + wm + ti * 16 + (lane >> 2);
        #pragma unroll
        for (int tj = 0; tj < 4; ++tj) {
            const int n0 = colBlock + wn + tj * 8 + (lane & 3) * 2;
            float2 v0 = make_float2(acc[ti][tj][0], acc[ti][tj][1]);
            float2 v1 = make_float2(acc[ti][tj][2], acc[ti][tj][3]);
            if (epi != 0) {
                const float bx = __ldg(bias + n0), by = __ldg(bias + n0 + 1);
                v0.x += bx; v0.y += by; v1.x += bx; v1.y += by;
                if (epi == 1) {
                    v0.x = fmaxf(v0.x, 0.f); v0.y = fmaxf(v0.y, 0.f);
                    v1.x = fmaxf(v1.x, 0.f); v1.y = fmaxf(v1.y, 0.f);
                }
            }
            const size_t p0 = offC + (size_t)m0 * 512 + n0;
            const size_t p1 = p0 + 8 * 512;
            if (epi == 2) {
                *(float2*)(Cf + p0) = v0;
                *(float2*)(Cf + p1) = v1;
            } else {
                __half2 h0 = __floats2half2_rn(v0.x, v0.y);
                __half2 h1 = __floats2half2_rn(v1.x, v1.y);
                *(uint32_t*)(Ch + p0) = *(uint32_t*)&h0;
                *(uint32_t*)(Ch + p1) = *(uint32_t*)&h1;
            }
        }
    }
}

__device__ __forceinline__ void spin_on(volatile int* p, int want) {
    while (*p < want) __nanosleep(32);
}

__global__ __launch_bounds__(256, 2)
void gcn_persistent(const float* __restrict__ Xf, const float* __restrict__ Jf,
                    __half* __restrict__ Xh, __half* __restrict__ Jh,
                    const __half* __restrict__ Wth,
                    __half* __restrict__ Sa, __half* __restrict__ Ha,
                    __half* __restrict__ Sb, __half* __restrict__ Hb,
                    __half* __restrict__ Sc,
                    const float* __restrict__ b0, const float* __restrict__ b1,
                    const float* __restrict__ b2,
                    float* __restrict__ out, int* __restrict__ cnt,
                    int* __restrict__ cflag, int* __restrict__ xflag)
{
    extern __shared__ char smem[];
    const uint32_t sb = smem_u32(smem);
    const int tid = threadIdx.x;
    const long s = 512l * 512l;

    const __half* Ap[6] = {Wth, Jh, Wth + s, Jh, Wth + 2 * s, Jh};
    const long    sA[6] = {0, s, 0, s, 0, s};
    const __half* Bp[6] = {Xh, Sa, Ha, Sb, Hb, Sc};
    __half*       Cp[6] = {Sa, Ha, Sb, Hb, Sc, nullptr};
    const float*  bi[6] = {nullptr, b0, nullptr, b1, nullptr, b2};
    const int     ep[6] = {0, 1, 0, 1, 0, 2};

    for (int g = blockIdx.x; g < 64 + 6 * 512; g += NCTA) {
        if (g < 64) {
            // conversion item: g<32 -> adj z-block, else X z-block
            const bool isJ = g < 32;
            const int z = g & 31;
            const float* in = (isJ ? Jf : Xf) + (size_t)z * s;
            __half* o = (isJ ? Jh : Xh) + (size_t)z * s;
            const int n4 = (int)(s / 4);     // 65536 float4
            for (int i = tid; i < n4; i += 256) {
                float4 v = ((const float4*)in)[i];
                __half2 h0 = __floats2half2_rn(v.x, v.y);
                __half2 h1 = __floats2half2_rn(v.z, v.w);
                ((uint2*)o)[i] = make_uint2(*(uint32_t*)&h0, *(uint32_t*)&h1);
            }
            __threadfence();
            __syncthreads();
            if (tid == 0) atomicExch((isJ ? cflag : xflag) + z, 1);
            continue;
        }

        const int gg = g - 64;
        const int stage = gg >> 9;
        const int t = gg & 511;
        const int z  = t >> 4;
        const int rb = (t >> 2) & 3;
        const int cb = t & 3;

        if (tid == 0) {
            if (stage == 0)            spin_on(xflag + z, 1);
            else {
                if (stage & 1)         spin_on(cflag + z, 1);   // adj stages 1,3,5
                spin_on(cnt + ((stage - 1) * 32 + z) * 4 + cb, 4);
            }
        }
        __syncthreads();
        __threadfence();   // acquire

        gemm_tile(Ap[stage], Bp[stage], bi[stage], out, Cp[stage],
                  sA[stage], z, rb, cb, ep[stage], sb);

        __threadfence();
        __syncthreads();
        if (tid == 0)
            atomicAdd(cnt + (stage * 32 + z) * 4 + rb, 1);
    }
}

// weight transpose (768 blocks) + counter zeroing (block 768)
__global__ __launch_bounds__(256)
void prep_w(const float* __restrict__ W0, const float* __restrict__ W1,
            const float* __restrict__ W2, __half* __restrict__ Wth,
            int* __restrict__ cnt, int* __restrict__ cflag,
            int* __restrict__ xflag)
{
    const int b = blockIdx.x;
    if (b == 768) {
        const int tid = threadIdx.x;
        for (int i = tid; i < 6 * 32 * 4; i += 256) cnt[i] = 0;
        if (tid < 32) { cflag[tid] = 0; xflag[tid] = 0; }
        return;
    }
    const int w = b >> 8;
    const int ti = b & 255;
    const float* in = (w == 0) ? W0 : (w == 1) ? W1 : W2;
    __half* o = Wth + (size_t)w * 512 * 512;
    const int bx = (ti & 15) * 32, by = (ti >> 4) * 32;
    const int x = threadIdx.x & 31, y = threadIdx.x >> 5;  // 32x8
    __shared__ float t[32][33];
    #pragma unroll
    for (int j = 0; j < 32; j += 8)
        t[y + j][x] = in[(size_t)(by + y + j) * 512 + bx + x];
    __syncthreads();
    #pragma unroll
    for (int j = 0; j < 32; j += 8)
        o[(size_t)(bx + y + j) * 512 + by + x] = __float2half_rn(t[x][y + j]);
}

extern "C" void kernel_launch(void* const* d_in, const int* in_sizes, int n_in,
                              void* d_out, int out_size)
{
    const float* X   = (const float*)d_in[0];
    const float* adj = (const float*)d_in[1];
    const float* W0  = (const float*)d_in[2];
    const float* b0  = (const float*)d_in[3];
    const float* W1  = (const float*)d_in[4];
    const float* b1  = (const float*)d_in[5];
    const float* W2  = (const float*)d_in[6];
    const float* b2  = (const float*)d_in[7];
    float* out = (float*)d_out;

    __half *Xh, *Jh, *Sa, *Ha, *Sb, *Hb, *Sc, *Wth;
    int *cnt, *cflag, *xflag;
    cudaGetSymbolAddress((void**)&Xh,  g_Xh);
    cudaGetSymbolAddress((void**)&Jh,  g_Jh);
    cudaGetSymbolAddress((void**)&Sa,  g_Sa);
    cudaGetSymbolAddress((void**)&Ha,  g_Ha);
    cudaGetSymbolAddress((void**)&Sb,  g_Sb);
    cudaGetSymbolAddress((void**)&Hb,  g_Hb);
    cudaGetSymbolAddress((void**)&Sc,  g_Sc);
    cudaGetSymbolAddress((void**)&Wth, g_Wth);
    cudaGetSymbolAddress((void**)&cnt, g_cnt);
    cudaGetSymbolAddress((void**)&cflag, g_cflag);
    cudaGetSymbolAddress((void**)&xflag, g_xflag);

    cudaFuncSetAttribute(gcn_persistent,
                         cudaFuncAttributeMaxDynamicSharedMemorySize, SMEM_BYTES);

    prep_w<<<769, 256>>>(W0, W1, W2, Wth, cnt, cflag, xflag);
    gcn_persistent<<<NCTA, 256, SMEM_BYTES>>>(X, adj, Xh, Jh, Wth,
                                              Sa, Ha, Sb, Hb, Sc,
                                              b0, b1, b2, out, cnt, cflag, xflag);
}

// round 17
// speedup vs baseline: 1.0853x; 1.0853x over previous
#include <cuda_runtime.h>
#include <cuda_fp16.h>
#include <cstdint>

// ============================================================
// GCN, all-fp16 mma.sync persistent kernel (R12 structure).
//  - preproc launch (full chip): X->fp16, W^T->fp16, zero counters
//  - persistent kernel: 32 adj-conversion items (slack-overlapped;
//    adj first consumed by stage 1) + 6x512 GEMM tiles
//  - single __syncthreads per K-chunk (R14-proven)
// Deps point to strictly lower g -> deadlock-free at 296 CTAs.
// ============================================================

static constexpr unsigned NE = 32u * 512u * 512u;
static constexpr unsigned NW = 512u * 512u;
static constexpr int NCTA = 296;

static __device__ __half g_Xh[NE], g_Jh[NE];
static __device__ __half g_Sa[NE], g_Ha[NE], g_Sb[NE], g_Hb[NE], g_Sc[NE];
static __device__ __half g_Wth[3 * NW];
static __device__ int    g_cnt[6 * 32 * 4];
static __device__ int    g_cflag[32];

__device__ __forceinline__ uint32_t smem_u32(const void* p) {
    uint32_t a;
    asm("{ .reg .u64 t; cvta.to.shared.u64 t, %1; cvt.u32.u64 %0, t; }"
        : "=r"(a) : "l"(p));
    return a;
}

#define LDSM_X4(r0, r1, r2, r3, addr) \
    asm volatile("ldmatrix.sync.aligned.m8n8.x4.shared.b16 {%0,%1,%2,%3}, [%4];" \
                 : "=r"(r0), "=r"(r1), "=r"(r2), "=r"(r3) : "r"(addr))

#define CP_ASYNC16(dst, src) \
    asm volatile("cp.async.cg.shared.global [%0], [%1], 16;" \
                 :: "r"(dst), "l"(src) : "memory")
#define CP_COMMIT() asm volatile("cp.async.commit_group;" ::: "memory")
#define CP_WAIT(n)  asm volatile("cp.async.wait_group %0;" :: "n"(n) : "memory")

__device__ __forceinline__ void mma16816(float* d, const uint32_t* a,
                                         uint32_t b0, uint32_t b1) {
    asm volatile(
        "mma.sync.aligned.m16n8k16.row.col.f32.f16.f16.f32 "
        "{%0,%1,%2,%3}, {%4,%5,%6,%7}, {%8,%9}, {%0,%1,%2,%3};"
        : "+f"(d[0]), "+f"(d[1]), "+f"(d[2]), "+f"(d[3])
        : "r"(a[0]), "r"(a[1]), "r"(a[2]), "r"(a[3]), "r"(b0), "r"(b1));
}

static constexpr int TILE = 128 * 64;             // 8KB (128 rows x 32 fp16)
static constexpr int OFF_A = 0, OFF_B = TILE;
static constexpr int STAGE_B = 2 * TILE;          // 16KB
static constexpr int NSTG  = 3;
static constexpr int SMEM_BYTES = NSTG * STAGE_B; // 48KB

__device__ __forceinline__ uint32_t sw_off(int row, int q) {
    return (uint32_t)row * 64u + (uint32_t)((q ^ ((row >> 1) & 3)) << 4);
}

// one 128x128 GEMM tile; epi: 0 plain->fp16, 1 bias+relu->fp16, 2 bias->fp32
__device__ __forceinline__
void gemm_tile(const __half* __restrict__ Ah, const __half* __restrict__ Bh,
               const float* __restrict__ bias,
               float* __restrict__ Cf, __half* __restrict__ Ch,
               long strideA, int z, int rb, int cb, int epi, uint32_t sb)
{
    const int tid  = threadIdx.x;
    const int wid  = tid >> 5;
    const int lane = tid & 31;
    const long s = 512l * 512l;
    const size_t offA = (size_t)z * strideA;
    const size_t offB = (size_t)z * s;
    const int rowBlock = rb * 128;
    const int colBlock = cb * 128;
    const int wm = (wid >> 2) * 64;
    const int wn = (wid & 3) * 32;

    const int cQ = tid & 3;
    uint32_t dOf[2];
    size_t gA[2], gB[2];
    #pragma unroll
    for (int i = 0; i < 2; ++i) {
        const int row = (tid >> 2) + i * 64;
        dOf[i] = sw_off(row, cQ);
        gA[i] = offA + (size_t)(rowBlock + row) * 512 + cQ * 8;
        gB[i] = offB + (size_t)(colBlock + row) * 512 + cQ * 8;
    }

    auto issue = [&](int c) {
        const uint32_t st = sb + (uint32_t)(c % NSTG) * STAGE_B;
        const int k0 = c * 32;
        #pragma unroll
        for (int i = 0; i < 2; ++i) {
            CP_ASYNC16(st + OFF_A + dOf[i], Ah + gA[i] + k0);
            CP_ASYNC16(st + OFF_B + dOf[i], Bh + gB[i] + k0);
        }
        CP_COMMIT();
    };

    const int lmRow = lane & 15;
    const int lmQ   = lane >> 4;
    uint32_t aRow[4], bRow[2];
    int aXr[4], bXr[2];
    #pragma unroll
    for (int ti = 0; ti < 4; ++ti) {
        const int r = wm + ti * 16 + lmRow;
        aRow[ti] = (uint32_t)r * 64u;
        aXr[ti]  = (r >> 1) & 3;
    }
    #pragma unroll
    for (int g = 0; g < 2; ++g) {
        const int r = wn + g * 16 + lmRow;
        bRow[g] = (uint32_t)r * 64u;
        bXr[g]  = (r >> 1) & 3;
    }

    float acc[4][4][4] = {};

    issue(0);
    issue(1);

    for (int c = 0; c < 16; ++c) {
        if (c == 15) { CP_WAIT(0); } else { CP_WAIT(1); }
        __syncthreads();       // orders stage reuse for issue(c+2) too
        if (c + 2 < 16) issue(c + 2);

        const uint32_t st = sb + (uint32_t)(c % NSTG) * STAGE_B;

        #pragma unroll
        for (int kk = 0; kk < 2; ++kk) {
            const int q = lmQ + kk * 2;
            uint32_t af[4][4], bb[2][4];
            #pragma unroll
            for (int g = 0; g < 2; ++g) {
                const uint32_t sw = (uint32_t)((q ^ bXr[g]) << 4);
                LDSM_X4(bb[g][0], bb[g][1], bb[g][2], bb[g][3],
                        st + OFF_B + bRow[g] + sw);
            }
            #pragma unroll
            for (int ti = 0; ti < 4; ++ti) {
                const uint32_t sw = (uint32_t)((q ^ aXr[ti]) << 4);
                LDSM_X4(af[ti][0], af[ti][1], af[ti][2], af[ti][3],
                        st + OFF_A + aRow[ti] + sw);
            }
            #pragma unroll
            for (int ti = 0; ti < 4; ++ti)
                #pragma unroll
                for (int tj = 0; tj < 4; ++tj)
                    mma16816(acc[ti][tj], af[ti],
                             bb[tj >> 1][tj & 1], bb[tj >> 1][2 + (tj & 1)]);
        }
    }

    const size_t offC = (size_t)z * s;
    #pragma unroll
    for (int ti = 0; ti < 4; ++ti) {
        const int m0 = rowBlock + wm + ti * 16 + (lane >> 2);
        #pragma unroll
        for (int tj = 0; tj < 4; ++tj) {
            const int n0 = colBlock + wn + tj * 8 + (lane & 3) * 2;
            float2 v0 = make_float2(acc[ti][tj][0], acc[ti][tj][1]);
            float2 v1 = make_float2(acc[ti][tj][2], acc[ti][tj][3]);
            if (epi != 0) {
                const float bx = __ldg(bias + n0), by = __ldg(bias + n0 + 1);
                v0.x += bx; v0.y += by; v1.x += bx; v1.y += by;
                if (epi == 1) {
                    v0.x = fmaxf(v0.x, 0.f); v0.y = fmaxf(v0.y, 0.f);
                    v1.x = fmaxf(v1.x, 0.f); v1.y = fmaxf(v1.y, 0.f);
                }
            }
            const size_t p0 = offC + (size_t)m0 * 512 + n0;
            const size_t p1 = p0 + 8 * 512;
            if (epi == 2) {
                *(float2*)(Cf + p0) = v0;
                *(float2*)(Cf + p1) = v1;
            } else {
                __half2 h0 = __floats2half2_rn(v0.x, v0.y);
                __half2 h1 = __floats2half2_rn(v1.x, v1.y);
                *(uint32_t*)(Ch + p0) = *(uint32_t*)&h0;
                *(uint32_t*)(Ch + p1) = *(uint32_t*)&h1;
            }
        }
    }
}

__device__ __forceinline__ void spin_on(volatile int* p, int want) {
    while (*p < want) __nanosleep(32);
}

__global__ __launch_bounds__(256, 2)
void gcn_persistent(const float* __restrict__ Jf,
                    const __half* __restrict__ Xh, __half* __restrict__ Jh,
                    const __half* __restrict__ Wth,
                    __half* __restrict__ Sa, __half* __restrict__ Ha,
                    __half* __restrict__ Sb, __half* __restrict__ Hb,
                    __half* __restrict__ Sc,
                    const float* __restrict__ b0, const float* __restrict__ b1,
                    const float* __restrict__ b2,
                    float* __restrict__ out, int* __restrict__ cnt,
                    int* __restrict__ cflag)
{
    extern __shared__ char smem[];
    const uint32_t sb = smem_u32(smem);
    const int tid = threadIdx.x;
    const long s = 512l * 512l;

    const __half* Ap[6] = {Wth, Jh, Wth + s, Jh, Wth + 2 * s, Jh};
    const long    sA[6] = {0, s, 0, s, 0, s};
    const __half* Bp[6] = {Xh, Sa, Ha, Sb, Hb, Sc};
    __half*       Cp[6] = {Sa, Ha, Sb, Hb, Sc, nullptr};
    const float*  bi[6] = {nullptr, b0, nullptr, b1, nullptr, b2};
    const int     ep[6] = {0, 1, 0, 1, 0, 2};

    for (int g = blockIdx.x; g < 32 + 6 * 512; g += NCTA) {
        if (g < 32) {
            // adj conversion item (consumed by stage 1: ~50us of slack)
            const int z = g;
            const float* in = Jf + (size_t)z * s;
            __half* o = Jh + (size_t)z * s;
            const int n4 = (int)(s / 4);
            for (int i = tid; i < n4; i += 256) {
                float4 v = ((const float4*)in)[i];
                __half2 h0 = __floats2half2_rn(v.x, v.y);
                __half2 h1 = __floats2half2_rn(v.z, v.w);
                ((uint2*)o)[i] = make_uint2(*(uint32_t*)&h0, *(uint32_t*)&h1);
            }
            __threadfence();
            __syncthreads();
            if (tid == 0) atomicExch(cflag + z, 1);
            continue;
        }

        const int gg = g - 32;
        const int stage = gg >> 9;
        const int t = gg & 511;
        const int z  = t >> 4;
        const int rb = (t >> 2) & 3;
        const int cb = t & 3;

        if (stage > 0) {
            if (tid == 0) {
                if (stage & 1) spin_on(cflag + z, 1);   // adj stages 1,3,5
                spin_on(cnt + ((stage - 1) * 32 + z) * 4 + cb, 4);
            }
            __syncthreads();
            __threadfence();   // acquire
        }

        gemm_tile(Ap[stage], Bp[stage], bi[stage], out, Cp[stage],
                  sA[stage], z, rb, cb, ep[stage], sb);

        __threadfence();
        __syncthreads();
        if (tid == 0)
            atomicAdd(cnt + (stage * 32 + z) * 4 + rb, 1);
    }
}

// full-chip preproc: X->fp16 (8192 blocks), W^T (768), zero counters (1)
__global__ __launch_bounds__(256)
void preproc(const float* __restrict__ X,
             const float* __restrict__ W0, const float* __restrict__ W1,
             const float* __restrict__ W2,
             __half* __restrict__ Xh, __half* __restrict__ Wth,
             int* __restrict__ cnt, int* __restrict__ cflag)
{
    const int b = blockIdx.x;
    const int tid = threadIdx.x;

    if (b < 8192) {            // X: 2M float4
        const int i = b * 256 + tid;
        float4 v = ((const float4*)X)[i];
        __half2 h0 = __floats2half2_rn(v.x, v.y);
        __half2 h1 = __floats2half2_rn(v.z, v.w);
        ((uint2*)Xh)[i] = make_uint2(*(uint32_t*)&h0, *(uint32_t*)&h1);
        return;
    }
    if (b == 8192 + 768) {     // counters
        for (int i = tid; i < 6 * 32 * 4; i += 256) cnt[i] = 0;
        if (tid < 32) cflag[tid] = 0;
        return;
    }
    // weight transpose: 3 x 256 tiles of 32x32
    const int tb = b - 8192;
    const int w  = tb >> 8;
    const int ti = tb & 255;
    const float* in = (w == 0) ? W0 : (w == 1) ? W1 : W2;
    __half* o = Wth + (size_t)w * 512 * 512;
    const int bx = (ti & 15) * 32, by = (ti >> 4) * 32;
    const int x = tid & 31, y = tid >> 5;   // 32x8
    __shared__ float t[32][33];
    #pragma unroll
    for (int j = 0; j < 32; j += 8)
        t[y + j][x] = in[(size_t)(by + y + j) * 512 + bx + x];
    __syncthreads();
    #pragma unroll
    for (int j = 0; j < 32; j += 8)
        o[(size_t)(bx + y + j) * 512 + by + x] = __float2half_rn(t[x][y + j]);
}

extern "C" void kernel_launch(void* const* d_in, const int* in_sizes, int n_in,
                              void* d_out, int out_size)
{
    const float* X   = (const float*)d_in[0];
    const float* adj = (const float*)d_in[1];
    const float* W0  = (const float*)d_in[2];
    const float* b0  = (const float*)d_in[3];
    const float* W1  = (const float*)d_in[4];
    const float* b1  = (const float*)d_in[5];
    const float* W2  = (const float*)d_in[6];
    const float* b2  = (const float*)d_in[7];
    float* out = (float*)d_out;

    __half *Xh, *Jh, *Sa, *Ha, *Sb, *Hb, *Sc, *Wth;
    int *cnt, *cflag;
    cudaGetSymbolAddress((void**)&Xh,  g_Xh);
    cudaGetSymbolAddress((void**)&Jh,  g_Jh);
    cudaGetSymbolAddress((void**)&Sa,  g_Sa);
    cudaGetSymbolAddress((void**)&Ha,  g_Ha);
    cudaGetSymbolAddress((void**)&Sb,  g_Sb);
    cudaGetSymbolAddress((void**)&Hb,  g_Hb);
    cudaGetSymbolAddress((void**)&Sc,  g_Sc);
    cudaGetSymbolAddress((void**)&Wth, g_Wth);
    cudaGetSymbolAddress((void**)&cnt, g_cnt);
    cudaGetSymbolAddress((void**)&cflag, g_cflag);

    cudaFuncSetAttribute(gcn_persistent,
                         cudaFuncAttributeMaxDynamicSharedMemorySize, SMEM_BYTES);

    preproc<<<8192 + 768 + 1, 256>>>(X, W0, W1, W2, Xh, Wth, cnt, cflag);
    gcn_persistent<<<NCTA, 256, SMEM_BYTES>>>(adj, Xh, Jh, Wth,
                                              Sa, Ha, Sb, Hb, Sc,
                                              b0, b1, b2, out, cnt, cflag);
}